// round 5
// baseline (speedup 1.0000x reference)
#include <cuda_runtime.h>
#include <cuda_bf16.h>
#include <math.h>

// ---------------- problem constants ----------------------------------------
#define NNODES   100000
#define NEDGES   1600000
#define NGRAPHS  200
#define NPG      500            // nodes per graph
#define INDIM    24
#define HID      64
#define LAT      32

#define MU_OFF      (NNODES * INDIM)            // 2,400,000
#define LV_OFF      (MU_OFF + NGRAPHS * LAT)    // 2,406,400

// ---------------- scratch (static device globals; no allocation) -----------
__device__ float         g_deg [NNODES];
__device__ float         g_dinv[NNODES];
__device__ float         g_w   [NEDGES];                 // per-edge norm weight
__device__ __nv_bfloat16 g_h1  [NNODES * HID];           // layer-1 linear out (bf16)
__device__ __nv_bfloat16 g_acc1[NNODES * HID];           // layer-1 aggregation (bf16)
__device__ __nv_bfloat16 g_h2  [NNODES * HID];
__device__ __nv_bfloat16 g_acc2[NNODES * HID];

// ---------------- helpers ---------------------------------------------------
__device__ __forceinline__ unsigned scl2(unsigned p, __nv_bfloat162 w2) {
    __nv_bfloat162 v = __hmul2(*reinterpret_cast<__nv_bfloat162*>(&p), w2);
    return *reinterpret_cast<unsigned*>(&v);
}

// ---------------- kernels ---------------------------------------------------

// deg = 1 (self loop)
__global__ void k_deg_init() {
    int i = blockIdx.x * blockDim.x + threadIdx.x;
    if (i < NNODES) g_deg[i] = 1.0f;
}

// deg[col[e]] += 1
__global__ void k_deg_count(const int* __restrict__ col) {
    int e = blockIdx.x * blockDim.x + threadIdx.x;
    if (e < NEDGES) atomicAdd(&g_deg[col[e]], 1.0f);
}

// dinv = rsqrt(deg)
__global__ void k_dinv() {
    int i = blockIdx.x * blockDim.x + threadIdx.x;
    if (i < NNODES) g_dinv[i] = rsqrtf(g_deg[i]);
}

// per-edge weight, computed once and reused by BOTH scatter layers
__global__ void k_edgew(const int* __restrict__ row, const int* __restrict__ col) {
    int e = blockIdx.x * blockDim.x + threadIdx.x;
    if (e < NEDGES) g_w[e] = g_dinv[row[e]] * g_dinv[col[e]];
}

// per node: h1 = x @ W1 (f32 compute, bf16 store); acc1 = h1 * dinv^2 (self loop)
// exactly NNODES*HID threads, 256/block -> 25000 blocks.
__global__ void k_enc1(const float* __restrict__ x, const float* __restrict__ W1) {
    __shared__ float Ws[INDIM * HID];
    for (int i = threadIdx.x; i < INDIM * HID; i += 256) Ws[i] = W1[i];
    __syncthreads();
    int tid = blockIdx.x * 256 + threadIdx.x;
    int n = tid >> 6, d = tid & 63;
    float di = g_dinv[n];
    const float* xr = x + n * INDIM;
    float s = 0.f;
#pragma unroll
    for (int k = 0; k < INDIM; k++) s = fmaf(__ldg(xr + k), Ws[k * HID + d], s);
    g_h1[tid]   = __float2bfloat16_rn(s);
    g_acc1[tid] = __float2bfloat16_rn(s * di * di);
}

// edge scatter: 8 threads per edge, each handles 16B = 8 bf16 dims.
// acc[col] += h[row] * w[e]  via red.global.add.noftz.v4.bf16x2
template <int LAYER>
__global__ void k_scatter(const int* __restrict__ row, const int* __restrict__ col) {
    int gt = blockIdx.x * 256 + threadIdx.x;   // < NEDGES*8 = 12.8M
    int e = gt >> 3;
    int j = gt & 7;
    if (e >= NEDGES) return;
    int r = row[e], c = col[e];
    __nv_bfloat162 w2 = __float2bfloat162_rn(g_w[e]);
    const uint4* hsrc = (LAYER == 1) ? (const uint4*)g_h1 : (const uint4*)g_h2;
    uint4*       adst = (LAYER == 1) ? (uint4*)g_acc1     : (uint4*)g_acc2;
    uint4 hv = hsrc[r * 8 + j];
    unsigned a0 = scl2(hv.x, w2), a1 = scl2(hv.y, w2);
    unsigned a2 = scl2(hv.z, w2), a3 = scl2(hv.w, w2);
    uint4* p = adst + (c * 8 + j);
    asm volatile("red.global.add.noftz.v4.bf16x2 [%0], {%1,%2,%3,%4};"
                 :: "l"(p), "r"(a0), "r"(a1), "r"(a2), "r"(a3)
                 : "memory");
}

// per node: h1 = relu(acc1 + b1); h2 = h1 @ W2; acc2 = h2 * dinv^2
__global__ void k_enc2(const float* __restrict__ b1, const float* __restrict__ W2) {
    __shared__ float Ws[HID * HID];   // 16 KB
    __shared__ float hs[4 * HID];
    for (int i = threadIdx.x; i < HID * HID; i += 256) Ws[i] = W2[i];
    int tid = blockIdx.x * 256 + threadIdx.x;   // exact: 25000 blocks
    int d  = tid & 63;
    int ln = threadIdx.x >> 6;                  // local node 0..3
    float h1 = fmaxf(__bfloat162float(g_acc1[tid]) + __ldg(b1 + d), 0.f);
    hs[ln * HID + d] = h1;
    __syncthreads();
    float s = 0.f;
#pragma unroll
    for (int k = 0; k < HID; k++) s = fmaf(hs[ln * HID + k], Ws[k * HID + d], s);
    int n = tid >> 6;
    float di = g_dinv[n];
    g_h2[tid]   = __float2bfloat16_rn(s);
    g_acc2[tid] = __float2bfloat16_rn(s * di * di);
}

// one block per graph: pool -> mu/logvar/z -> decoder (one row) -> broadcast.
__global__ void k_final(const float* __restrict__ b2,  const float* __restrict__ eps,
                        const float* __restrict__ Wmu, const float* __restrict__ bmu,
                        const float* __restrict__ Wlv, const float* __restrict__ blv,
                        const float* __restrict__ Wd1, const float* __restrict__ bd1,
                        const float* __restrict__ Wd2, const float* __restrict__ bd2,
                        float* __restrict__ out) {
    int g = blockIdx.x;
    int t = threadIdx.x;
    __shared__ float part[256];
    __shared__ float pool[HID];
    __shared__ float zs[LAT];
    __shared__ float hd[128];
    __shared__ float rc[INDIM];

    // --- mean pool of relu(acc2 + b2) over this graph's 500 nodes ---
    int d   = t & 63;
    int grp = t >> 6;                            // 0..3
    const __nv_bfloat16* base = g_acc2 + (size_t)g * NPG * HID;
    float bb = __ldg(b2 + d);
    float s = 0.f;
    for (int n = grp; n < NPG; n += 4)
        s += fmaxf(__bfloat162float(base[n * HID + d]) + bb, 0.f);
    part[t] = s;
    __syncthreads();
    if (grp == 0)
        pool[d] = (part[d] + part[64 + d] + part[128 + d] + part[192 + d]) * (1.0f / NPG);
    __syncthreads();

    // --- mu, logvar, z ---
    if (t < LAT) {
        float mu = __ldg(bmu + t), lv = __ldg(blv + t);
#pragma unroll
        for (int k = 0; k < HID; k++) {
            float pk = pool[k];
            mu = fmaf(pk, __ldg(Wmu + k * LAT + t), mu);
            lv = fmaf(pk, __ldg(Wlv + k * LAT + t), lv);
        }
        out[MU_OFF + g * LAT + t] = mu;
        out[LV_OFF + g * LAT + t] = lv;
        zs[t] = mu + __ldg(eps + g * LAT + t) * expf(0.5f * lv);
    }
    __syncthreads();

    // --- decoder layer 1 (128) ---
    if (t < 128) {
        float a = __ldg(bd1 + t);
#pragma unroll
        for (int k = 0; k < LAT; k++) a = fmaf(zs[k], __ldg(Wd1 + k * 128 + t), a);
        hd[t] = fmaxf(a, 0.f);
    }
    __syncthreads();

    // --- decoder layer 2 (24) + sigmoid ---
    if (t < INDIM) {
        float a = __ldg(bd2 + t);
#pragma unroll
        for (int k = 0; k < 128; k++) a = fmaf(hd[k], __ldg(Wd2 + k * INDIM + t), a);
        rc[t] = 1.0f / (1.0f + expf(-a));
    }
    __syncthreads();

    // --- broadcast the single recon row to all 500 node rows ---
    float* orow = out + (size_t)g * NPG * INDIM;
    for (int i = t; i < NPG * INDIM; i += 256) orow[i] = rc[i % INDIM];
}

// ---------------- launch ----------------------------------------------------
extern "C" void kernel_launch(void* const* d_in, const int* in_sizes, int n_in,
                              void* d_out, int out_size) {
    const float* x   = (const float*)d_in[0];
    const int*   ei  = (const int*)  d_in[1];   // [2, E]
    // d_in[2] = batch (unused: batch[i] == i / NPG by construction)
    const float* eps = (const float*)d_in[3];
    const float* W1  = (const float*)d_in[4];
    const float* b1  = (const float*)d_in[5];
    const float* W2  = (const float*)d_in[6];
    const float* b2  = (const float*)d_in[7];
    const float* Wmu = (const float*)d_in[8];
    const float* bmu = (const float*)d_in[9];
    const float* Wlv = (const float*)d_in[10];
    const float* blv = (const float*)d_in[11];
    const float* Wd1 = (const float*)d_in[12];
    const float* bd1 = (const float*)d_in[13];
    const float* Wd2 = (const float*)d_in[14];
    const float* bd2 = (const float*)d_in[15];
    float* out = (float*)d_out;

    const int* row = ei;
    const int* col = ei + NEDGES;

    k_deg_init <<<(NNODES + 255) / 256, 256>>>();
    k_deg_count<<<(NEDGES + 255) / 256, 256>>>(col);
    k_dinv     <<<(NNODES + 255) / 256, 256>>>();
    k_edgew    <<<(NEDGES + 255) / 256, 256>>>(row, col);
    k_enc1     <<<NNODES * HID / 256, 256>>>(x, W1);              // 25000 blocks
    k_scatter<1><<<NEDGES * 8 / 256, 256>>>(row, col);            // 50000 blocks
    k_enc2     <<<NNODES * HID / 256, 256>>>(b1, W2);
    k_scatter<2><<<NEDGES * 8 / 256, 256>>>(row, col);
    k_final    <<<NGRAPHS, 256>>>(b2, eps, Wmu, bmu, Wlv, blv,
                                  Wd1, bd1, Wd2, bd2, out);
}

// round 6
// speedup vs baseline: 1.1859x; 1.1859x over previous
#include <cuda_runtime.h>
#include <math.h>

// ---------------- problem constants ----------------------------------------
#define NNODES   100000
#define NEDGES   1600000
#define NGRAPHS  200
#define NPG      500            // nodes per graph
#define INDIM    24
#define HID      64
#define LAT      32

#define MU_OFF      (NNODES * INDIM)            // 2,400,000
#define LV_OFF      (MU_OFF + NGRAPHS * LAT)    // 2,406,400

#define NB_SCAN  ((NNODES + 1023) / 1024)       // 98 scan blocks

// ---------------- scratch (static device globals; no allocation) -----------
__device__ int   g_cnt [NNODES];        // in-degree (excluding self loop)
__device__ int   g_cur [NNODES];        // fill cursor
__device__ int   g_off [NNODES];        // CSR exclusive offsets
__device__ int   g_bsum[NB_SCAN];
__device__ int   g_bpre[NB_SCAN];
__device__ float g_dinv[NNODES];
__device__ int2  g_edge[NEDGES];        // {src, weight-as-bits}, grouped by dst
__device__ float g_h1  [NNODES * HID];  // layer-1 linear out
__device__ float g_a1  [NNODES * HID];  // relu(agg1 + b1)
__device__ float g_h2  [NNODES * HID];  // layer-2 linear out
__device__ float g_pool[NGRAPHS * HID]; // pooled sums

// ---------------- CSR build -------------------------------------------------

__global__ void k_clear() {
    int i = blockIdx.x * blockDim.x + threadIdx.x;
    if (i < NNODES) { g_cnt[i] = 0; g_cur[i] = 0; }
    if (i < NGRAPHS * HID) g_pool[i] = 0.f;
}

__global__ void k_count(const int* __restrict__ col) {
    int e = blockIdx.x * blockDim.x + threadIdx.x;
    if (e < NEDGES) atomicAdd(&g_cnt[col[e]], 1);
}

// dinv = rsqrt(in_degree + 1 self loop)
__global__ void k_dinv() {
    int i = blockIdx.x * blockDim.x + threadIdx.x;
    if (i < NNODES) g_dinv[i] = rsqrtf((float)g_cnt[i] + 1.0f);
}

// per-block exclusive scan of cnt -> off (local), block totals -> bsum
__global__ void k_scan1() {
    __shared__ int sh[1024];
    int t = threadIdx.x;
    int i = blockIdx.x * 1024 + t;
    int v = (i < NNODES) ? g_cnt[i] : 0;
    sh[t] = v;
    __syncthreads();
#pragma unroll
    for (int s = 1; s < 1024; s <<= 1) {
        int u = (t >= s) ? sh[t - s] : 0;
        __syncthreads();
        sh[t] += u;
        __syncthreads();
    }
    if (i < NNODES) g_off[i] = sh[t] - v;       // exclusive within block
    if (t == 1023) g_bsum[blockIdx.x] = sh[1023];
}

__global__ void k_scan2() {
    if (threadIdx.x == 0) {
        int run = 0;
        for (int b = 0; b < NB_SCAN; b++) { g_bpre[b] = run; run += g_bsum[b]; }
    }
}

__global__ void k_scan3() {
    int i = blockIdx.x * blockDim.x + threadIdx.x;
    if (i < NNODES) g_off[i] += g_bpre[i >> 10];
}

// fill CSR: g_edge[pos] = {src, w} grouped by destination node
__global__ void k_fill(const int* __restrict__ row, const int* __restrict__ col) {
    int e = blockIdx.x * blockDim.x + threadIdx.x;
    if (e >= NEDGES) return;
    int r = row[e], c = col[e];
    float w = g_dinv[r] * g_dinv[c];
    int pos = g_off[c] + atomicAdd(&g_cur[c], 1);
    g_edge[pos] = make_int2(r, __float_as_int(w));
}

// ---------------- encoder linears -------------------------------------------

// h1 = x @ W1 (no bias yet; bias+relu applied after aggregation)
__global__ void k_enc1(const float* __restrict__ x, const float* __restrict__ W1) {
    __shared__ float Ws[INDIM * HID];
    for (int i = threadIdx.x; i < INDIM * HID; i += 256) Ws[i] = W1[i];
    __syncthreads();
    int tid = blockIdx.x * 256 + threadIdx.x;   // exact 25000 blocks
    int n = tid >> 6, d = tid & 63;
    const float* xr = x + n * INDIM;
    float s = 0.f;
#pragma unroll
    for (int k = 0; k < INDIM; k++) s = fmaf(__ldg(xr + k), Ws[k * HID + d], s);
    g_h1[tid] = s;
}

// h2 = a1 @ W2
__global__ void k_enc2(const float* __restrict__ W2) {
    __shared__ float Ws[HID * HID];   // 16 KB
    __shared__ float hs[4 * HID];
    for (int i = threadIdx.x; i < HID * HID; i += 256) Ws[i] = W2[i];
    int tid = blockIdx.x * 256 + threadIdx.x;   // exact 25000 blocks
    int d  = tid & 63;
    int ln = threadIdx.x >> 6;
    hs[ln * HID + d] = g_a1[tid];
    __syncthreads();
    float s = 0.f;
#pragma unroll
    for (int k = 0; k < HID; k++) s = fmaf(hs[ln * HID + k], Ws[k * HID + d], s);
    g_h2[tid] = s;
}

// ---------------- gather-based aggregation (one warp per node) --------------
// acc = h[n]*dinv[n]^2 + sum_in h[src]*w ; f32 accumulation, no atomics on acc.
// LAYER 1 epilogue: a1 = relu(acc + b1)
// LAYER 2 epilogue: pool[g] += relu(acc + b2)   (low-contention f32 atomics)
template <int LAYER>
__global__ void k_agg(const float* __restrict__ bias) {
    int n    = (blockIdx.x * 256 + threadIdx.x) >> 5;  // exact: 12500*8 = 100000
    int lane = threadIdx.x & 31;
    const float2* h = (const float2*)(LAYER == 1 ? g_h1 : g_h2);
    float di = g_dinv[n];
    float2 hv = h[n * 32 + lane];
    float2 acc = make_float2(hv.x * di * di, hv.y * di * di);
    int off = g_off[n], cnt = g_cnt[n];
#pragma unroll 2
    for (int e = 0; e < cnt; e++) {
        int2 ed = __ldg(&g_edge[off + e]);             // warp-broadcast load
        float w = __int_as_float(ed.y);
        float2 s = h[ed.x * 32 + lane];                // coalesced 256B gather
        acc.x = fmaf(s.x, w, acc.x);
        acc.y = fmaf(s.y, w, acc.y);
    }
    float b0 = __ldg(bias + 2 * lane), b1 = __ldg(bias + 2 * lane + 1);
    float v0 = fmaxf(acc.x + b0, 0.f);
    float v1 = fmaxf(acc.y + b1, 0.f);
    if (LAYER == 1) {
        ((float2*)g_a1)[n * 32 + lane] = make_float2(v0, v1);
    } else {
        int g = n / NPG;
        atomicAdd(&g_pool[g * HID + 2 * lane],     v0);
        atomicAdd(&g_pool[g * HID + 2 * lane + 1], v1);
    }
}

// ---------------- head: mu/logvar/z -> decoder row -> broadcast --------------
__global__ void k_final(const float* __restrict__ eps,
                        const float* __restrict__ Wmu, const float* __restrict__ bmu,
                        const float* __restrict__ Wlv, const float* __restrict__ blv,
                        const float* __restrict__ Wd1, const float* __restrict__ bd1,
                        const float* __restrict__ Wd2, const float* __restrict__ bd2,
                        float* __restrict__ out) {
    int g = blockIdx.x;
    int t = threadIdx.x;   // 128 threads
    __shared__ float pool[HID];
    __shared__ float zs[LAT];
    __shared__ float hd[128];
    __shared__ float rc[INDIM];

    if (t < HID) pool[t] = g_pool[g * HID + t] * (1.0f / NPG);
    __syncthreads();

    if (t < LAT) {
        float mu = __ldg(bmu + t), lv = __ldg(blv + t);
#pragma unroll
        for (int k = 0; k < HID; k++) {
            float pk = pool[k];
            mu = fmaf(pk, __ldg(Wmu + k * LAT + t), mu);
            lv = fmaf(pk, __ldg(Wlv + k * LAT + t), lv);
        }
        out[MU_OFF + g * LAT + t] = mu;
        out[LV_OFF + g * LAT + t] = lv;
        zs[t] = mu + __ldg(eps + g * LAT + t) * expf(0.5f * lv);
    }
    __syncthreads();

    {   // decoder layer 1 (128 units)
        float a = __ldg(bd1 + t);
#pragma unroll
        for (int k = 0; k < LAT; k++) a = fmaf(zs[k], __ldg(Wd1 + k * 128 + t), a);
        hd[t] = fmaxf(a, 0.f);
    }
    __syncthreads();

    if (t < INDIM) {   // decoder layer 2 (24) + sigmoid
        float a = __ldg(bd2 + t);
#pragma unroll
        for (int k = 0; k < 128; k++) a = fmaf(hd[k], __ldg(Wd2 + k * INDIM + t), a);
        rc[t] = 1.0f / (1.0f + expf(-a));
    }
    __syncthreads();

    float* orow = out + (size_t)g * NPG * INDIM;
    for (int i = t; i < NPG * INDIM; i += 128) orow[i] = rc[i % INDIM];
}

// ---------------- launch ----------------------------------------------------
extern "C" void kernel_launch(void* const* d_in, const int* in_sizes, int n_in,
                              void* d_out, int out_size) {
    const float* x   = (const float*)d_in[0];
    const int*   ei  = (const int*)  d_in[1];   // [2, E]
    // d_in[2] = batch (unused: batch[i] == i / NPG by construction)
    const float* eps = (const float*)d_in[3];
    const float* W1  = (const float*)d_in[4];
    // b1 = d_in[5] folded into k_agg<1>
    const float* b1  = (const float*)d_in[5];
    const float* W2  = (const float*)d_in[6];
    const float* b2  = (const float*)d_in[7];
    const float* Wmu = (const float*)d_in[8];
    const float* bmu = (const float*)d_in[9];
    const float* Wlv = (const float*)d_in[10];
    const float* blv = (const float*)d_in[11];
    const float* Wd1 = (const float*)d_in[12];
    const float* bd1 = (const float*)d_in[13];
    const float* Wd2 = (const float*)d_in[14];
    const float* bd2 = (const float*)d_in[15];
    float* out = (float*)d_out;

    const int* row = ei;
    const int* col = ei + NEDGES;

    // CSR build
    k_clear<<<(NNODES + 255) / 256, 256>>>();
    k_count<<<(NEDGES + 255) / 256, 256>>>(col);
    k_dinv <<<(NNODES + 255) / 256, 256>>>();
    k_scan1<<<NB_SCAN, 1024>>>();
    k_scan2<<<1, 32>>>();
    k_scan3<<<(NNODES + 255) / 256, 256>>>();
    k_fill <<<(NEDGES + 255) / 256, 256>>>(row, col);

    // encoder
    k_enc1  <<<NNODES * HID / 256, 256>>>(x, W1);   // 25000 blocks
    k_agg<1><<<NNODES * 32 / 256, 256>>>(b1);       // 12500 blocks, warp/node
    k_enc2  <<<NNODES * HID / 256, 256>>>(W2);
    k_agg<2><<<NNODES * 32 / 256, 256>>>(b2);

    // head + decoder + broadcast
    k_final<<<NGRAPHS, 128>>>(eps, Wmu, bmu, Wlv, blv, Wd1, bd1, Wd2, bd2, out);
}